// round 6
// baseline (speedup 1.0000x reference)
#include <cuda_runtime.h>

#define B 64
#define N 16384
#define M 64
#define FULLM 0xFFFFFFFFu

#define NBLK 148
#define NTHR 1024

#define ROWS_PER_TILE 256
#define NTILE 4096            // (B*N)/256
#define NCHUNK 8192           // (B*N)/128 ; 128 elems per warp-chunk
#define NWARPS_GRID (NBLK * 32)

// scratch (device globals — no allocation allowed)
__device__ float g_s[B * N];          // exp(beta*cos)
__device__ float g_tilesum[NTILE];    // per-tile partial softmax sums
__device__ float g_pp[NCHUNK];        // per-chunk partial renorm sums
__device__ unsigned g_c1, g_c2;       // grid-sync counters (monotonic)

// Grid-wide sync. Safe: grid == 148 blocks, 1024 thr, 1 block/SM -> all
// co-resident in wave 1. Counters are monotonic across graph replays:
// target derived from epoch = v / NBLK (replays serialize, so all blocks of
// one launch share an epoch).
__device__ __forceinline__ void grid_sync(unsigned* ctr) {
    __syncthreads();
    if (threadIdx.x == 0) {
        __threadfence();
        const unsigned v = atomicAdd(ctr, 1u);
        const unsigned target = (v / NBLK + 1u) * NBLK;
        while (atomicAdd(ctr, 0u) < target) { __nanosleep(64); }
        __threadfence();
    }
    __syncthreads();
}

__global__ __launch_bounds__(NTHR, 1) void ntm_fused(
    const float* __restrict__ key,      // [B,M]
    const float* __restrict__ beta,     // [B,1]
    const float* __restrict__ gate,     // [B,1]
    const float* __restrict__ shift,    // [B,3]
    const float* __restrict__ sharpen,  // [B,1]
    const float* __restrict__ last,     // [B,N]
    const float* __restrict__ mem,      // [B,N,M]
    float* __restrict__ out)            // [B,N]
{
    const int tid  = threadIdx.x;
    const int warp = tid >> 5;
    const int lane = tid & 31;

    __shared__ float red[32];

    // =========================== Phase 1: logits ===========================
    // 8 lanes/row (each lane: 2 float4 = 32B of the 256B row), 2 rows/thread.
    // Tile = 256 rows handled by 1024 threads.
    {
        const int l   = tid & 7;   // lane within 8-lane row group
        const int grp = tid >> 3;  // 0..127

        for (int t = blockIdx.x; t < NTILE; t += NBLK) {
            const int b    = t >> 6;                 // 64 tiles per batch
            const int row0 = (t & 63) * ROWS_PER_TILE;

            const float4* kp = reinterpret_cast<const float4*>(key + b * M);
            const float4 ka = kp[l];
            const float4 kb = kp[l + 8];
            float ks = ka.x * ka.x + ka.y * ka.y + ka.z * ka.z + ka.w * ka.w
                     + kb.x * kb.x + kb.y * kb.y + kb.z * kb.z + kb.w * kb.w;

            // front-batched streaming loads (4 LDG.128.CS per thread)
            float4 ma[2], mb[2];
#pragma unroll
            for (int u = 0; u < 2; ++u) {
                const int row = row0 + u * 128 + grp;
                const float4* mp = reinterpret_cast<const float4*>(
                    mem + ((size_t)b * N + row) * M);
                ma[u] = __ldcs(mp + l);
                mb[u] = __ldcs(mp + l + 8);
            }

            float dt[2], ms[2];
#pragma unroll
            for (int u = 0; u < 2; ++u) {
                dt[u] = ka.x * ma[u].x + ka.y * ma[u].y + ka.z * ma[u].z + ka.w * ma[u].w
                      + kb.x * mb[u].x + kb.y * mb[u].y + kb.z * mb[u].z + kb.w * mb[u].w;
                ms[u] = ma[u].x * ma[u].x + ma[u].y * ma[u].y + ma[u].z * ma[u].z + ma[u].w * ma[u].w
                      + mb[u].x * mb[u].x + mb[u].y * mb[u].y + mb[u].z * mb[u].z + mb[u].w * mb[u].w;
            }

#pragma unroll
            for (int off = 1; off <= 4; off <<= 1) {
                ks    += __shfl_xor_sync(FULLM, ks,    off);
                dt[0] += __shfl_xor_sync(FULLM, dt[0], off);
                dt[1] += __shfl_xor_sync(FULLM, dt[1], off);
                ms[0] += __shfl_xor_sync(FULLM, ms[0], off);
                ms[1] += __shfl_xor_sync(FULLM, ms[1], off);
            }

            float esum = 0.0f;
            if (l == 0) {
                const float kn = sqrtf(ks);
                const float be = __ldg(beta + b);
#pragma unroll
                for (int u = 0; u < 2; ++u) {
                    const int row = row0 + u * 128 + grp;
                    const float denom = fmaxf(kn * sqrtf(ms[u]), 1e-8f);
                    const float e = __expf(be * (dt[u] / denom));
                    g_s[b * N + row] = e;
                    esum += e;
                }
            }

            // deterministic block reduce -> g_tilesum[t]
#pragma unroll
            for (int o = 16; o > 0; o >>= 1)
                esum += __shfl_xor_sync(FULLM, esum, o);
            if (lane == 0) red[warp] = esum;
            __syncthreads();
            if (tid < 32) {
                float x = red[tid];
#pragma unroll
                for (int o = 16; o > 0; o >>= 1)
                    x += __shfl_xor_sync(FULLM, x, o);
                if (tid == 0) g_tilesum[t] = x;
            }
            __syncthreads();
        }
    }

    grid_sync(&g_c1);

    // ==================== Phase 2: gate + shift + pow =====================
    // Warp-chunks of 128 elems (32 float4). Softmax denom re-reduced from
    // tile partials per warp (L2-hot). Results kept in registers.
    const int gw = blockIdx.x * 32 + warp;  // 0..4735
    float4 p4[2];
    int    cid[2];
    int    nc = 0;

    for (int c = gw; c < NCHUNK; c += NWARPS_GRID) {
        const int b = c >> 7;  // 128 chunks per batch

        // softmax denominator for batch b (xor-reduce -> all lanes)
        float S = g_tilesum[(b << 6) + lane] + g_tilesum[(b << 6) + 32 + lane];
#pragma unroll
        for (int o = 16; o > 0; o >>= 1)
            S += __shfl_xor_sync(FULLM, S, o);

        const float g  = __ldg(gate + b);
        const float gS = g / S;
        const float og = 1.0f - g;
        const float s0 = __ldg(shift + b * 3 + 0);
        const float s1 = __ldg(shift + b * 3 + 1);
        const float s2 = __ldg(shift + b * 3 + 2);
        const float sh = __ldg(sharpen + b);

        const int li4 = (c & 127) * 32 + lane;   // batch-local float4 idx
        const int i4  = (b << 12) + li4;         // global float4 idx
        const float4 e4 = reinterpret_cast<const float4*>(g_s)[i4];
        const float4 a4 = reinterpret_cast<const float4*>(last)[i4];

        const int base = b * N;
        const int eoff = li4 * 4;
        const int lidx = base + ((eoff + N - 1) & (N - 1));
        const int ridx = base + ((eoff + 4) & (N - 1));
        const float wl = fmaf(gS, g_s[lidx], og * last[lidx]);
        const float wr = fmaf(gS, g_s[ridx], og * last[ridx]);

        float4 w;
        w.x = fmaf(gS, e4.x, og * a4.x);
        w.y = fmaf(gS, e4.y, og * a4.y);
        w.z = fmaf(gS, e4.z, og * a4.z);
        w.w = fmaf(gS, e4.w, og * a4.w);

        float4 p;
        p.x = __powf(s0 * wl  + s1 * w.x + s2 * w.y, sh);
        p.y = __powf(s0 * w.x + s1 * w.y + s2 * w.z, sh);
        p.z = __powf(s0 * w.y + s1 * w.z + s2 * w.w, sh);
        p.w = __powf(s0 * w.z + s1 * w.w + s2 * wr,  sh);

        float ps = p.x + p.y + p.z + p.w;
#pragma unroll
        for (int o = 16; o > 0; o >>= 1)
            ps += __shfl_xor_sync(FULLM, ps, o);
        if (lane == 0) g_pp[c] = ps;

        p4[nc] = p;
        cid[nc] = c;
        ++nc;
    }

    grid_sync(&g_c2);

    // ======================= Phase 3: renormalize =========================
    for (int j = 0; j < nc; ++j) {
        const int c = cid[j];
        const int b = c >> 7;
        float P = g_pp[(b << 7) + lane]      + g_pp[(b << 7) + 32 + lane]
                + g_pp[(b << 7) + 64 + lane] + g_pp[(b << 7) + 96 + lane];
#pragma unroll
        for (int o = 16; o > 0; o >>= 1)
            P += __shfl_xor_sync(FULLM, P, o);
        const float invP = 1.0f / (P + 1e-16f);

        const int i4 = (b << 12) + (c & 127) * 32 + lane;
        float4 p = p4[j];
        p.x *= invP; p.y *= invP; p.z *= invP; p.w *= invP;
        reinterpret_cast<float4*>(out)[i4] = p;
    }
}

extern "C" void kernel_launch(void* const* d_in, const int* in_sizes, int n_in,
                              void* d_out, int out_size) {
    const float* key     = (const float*)d_in[0];
    const float* beta    = (const float*)d_in[1];
    const float* gate    = (const float*)d_in[2];
    const float* shift   = (const float*)d_in[3];
    const float* sharpen = (const float*)d_in[4];
    const float* last    = (const float*)d_in[5];
    const float* mem     = (const float*)d_in[6];
    float* out = (float*)d_out;

    ntm_fused<<<NBLK, NTHR>>>(key, beta, gate, shift, sharpen, last, mem, out);
}

// round 7
// speedup vs baseline: 1.0325x; 1.0325x over previous
#include <cuda_runtime.h>

#define B 64
#define N 16384
#define M 64
#define FULLM 0xFFFFFFFFu

// scratch (device globals — no allocation allowed; zero-initialized)
__device__ float    g_s[B * N];        // exp(beta*cos)
__device__ float    g_tilesum[B * 64]; // per-tile partial softmax sums
__device__ unsigned g_cnt[B];          // per-batch completion counters (monotonic)

// ---------------------------------------------------------------------------
// Single kernel. Grid (64 tiles, 64 batches), 256 threads.
// Phase A (all blocks): tile of 256 rows -> exp(beta*cos) + tile partial sum.
//   4 lanes/row, lane loads 4x float4 (64B of 256B row), 4 rows/thread ->
//   16 LDG.128.CS in flight. Identical to the best R4 k1.
// Phase B (last block per batch): full batch epilogue — softmax denom from
//   the 64 tile partials, gate + circular 3-tap shift (elementwise recompute,
//   L2-hot) + sharpen (results in registers), renorm, store. Overlaps with
//   other batches' Phase A streaming.
// ---------------------------------------------------------------------------
__global__ __launch_bounds__(256) void ntm_kernel(
    const float* __restrict__ key,      // [B,M]
    const float* __restrict__ beta,     // [B,1]
    const float* __restrict__ gate,     // [B,1]
    const float* __restrict__ shift,    // [B,3]
    const float* __restrict__ sharpen,  // [B,1]
    const float* __restrict__ last,     // [B,N]
    const float* __restrict__ mem,      // [B,N,M]
    float* __restrict__ out)            // [B,N]
{
    const int b    = blockIdx.y;
    const int tid  = threadIdx.x;
    const int lane = tid & 31;

    __shared__ float sred[8];
    __shared__ float sbc;
    __shared__ int   slast;

    // =========================== Phase A ===========================
    {
        const int l    = tid & 3;    // lane within 4-lane row group
        const int grp  = tid >> 2;   // 0..63
        const int row0 = blockIdx.x * 256;

        const float4* kp = reinterpret_cast<const float4*>(key + b * M);
        float4 k4[4];
#pragma unroll
        for (int j = 0; j < 4; ++j) k4[j] = kp[l + 4 * j];

        float ks = 0.0f;
#pragma unroll
        for (int j = 0; j < 4; ++j)
            ks += k4[j].x * k4[j].x + k4[j].y * k4[j].y
                + k4[j].z * k4[j].z + k4[j].w * k4[j].w;

        // front-batched streaming loads: 16 LDG.128.CS in flight
        float4 m4[4][4];
#pragma unroll
        for (int u = 0; u < 4; ++u) {
            const int row = row0 + u * 64 + grp;
            const float4* mp = reinterpret_cast<const float4*>(
                mem + ((size_t)b * N + row) * M);
#pragma unroll
            for (int j = 0; j < 4; ++j) m4[u][j] = __ldcs(mp + l + 4 * j);
        }

        float dt[4] = {0.f, 0.f, 0.f, 0.f}, ms[4] = {0.f, 0.f, 0.f, 0.f};
#pragma unroll
        for (int u = 0; u < 4; ++u)
#pragma unroll
            for (int j = 0; j < 4; ++j) {
                dt[u] += k4[j].x * m4[u][j].x + k4[j].y * m4[u][j].y
                       + k4[j].z * m4[u][j].z + k4[j].w * m4[u][j].w;
                ms[u] += m4[u][j].x * m4[u][j].x + m4[u][j].y * m4[u][j].y
                       + m4[u][j].z * m4[u][j].z + m4[u][j].w * m4[u][j].w;
            }

#pragma unroll
        for (int off = 1; off <= 2; off <<= 1) {
            ks += __shfl_xor_sync(FULLM, ks, off);
#pragma unroll
            for (int u = 0; u < 4; ++u) {
                dt[u] += __shfl_xor_sync(FULLM, dt[u], off);
                ms[u] += __shfl_xor_sync(FULLM, ms[u], off);
            }
        }

        float esum = 0.0f;
        if (l == 0) {
            const float kn = sqrtf(ks);
            const float be = __ldg(beta + b);
#pragma unroll
            for (int u = 0; u < 4; ++u) {
                const int row = row0 + u * 64 + grp;
                const float denom = fmaxf(kn * sqrtf(ms[u]), 1e-8f);
                const float e = __expf(be * (dt[u] / denom));
                g_s[b * N + row] = e;
                esum += e;
            }
        }

        // deterministic block reduce -> g_tilesum
#pragma unroll
        for (int o = 16; o > 0; o >>= 1)
            esum += __shfl_xor_sync(FULLM, esum, o);
        if (lane == 0) sred[tid >> 5] = esum;
        __syncthreads();
        if (tid == 0) {
            float s = 0.0f;
#pragma unroll
            for (int w = 0; w < 8; ++w) s += sred[w];
            g_tilesum[b * 64 + blockIdx.x] = s;
        }
    }

    // ---- completion handshake (threadFenceReduction pattern) ----
    __threadfence();
    __syncthreads();
    if (tid == 0) {
        const unsigned old = atomicAdd(&g_cnt[b], 1u);
        slast = ((old & 63u) == 63u) ? 1 : 0;
    }
    __syncthreads();
    if (!slast) return;
    __threadfence();  // acquire: make peers' g_s / g_tilesum writes visible

    // =========================== Phase B ===========================
    // This block owns the whole batch-b epilogue. 256 threads, 16 float4 each.
    float S = 0.0f;
    const float* ts = g_tilesum + b * 64;
#pragma unroll
    for (int j = 0; j < 64; ++j) S += ts[j];   // fixed order -> deterministic

    const float g  = __ldg(gate + b);
    const float gS = g / S;
    const float og = 1.0f - g;
    const float s0 = __ldg(shift + b * 3 + 0);
    const float s1 = __ldg(shift + b * 3 + 1);
    const float s2 = __ldg(shift + b * 3 + 2);
    const float sh = __ldg(sharpen + b);

    const float4* sp4 = reinterpret_cast<const float4*>(g_s  + b * N);
    const float4* lp4 = reinterpret_cast<const float4*>(last + (size_t)b * N);
    const float*  sp  = g_s  + b * N;
    const float*  lp  = last + (size_t)b * N;

    float4 p4[16];
    float psum = 0.0f;
#pragma unroll
    for (int k = 0; k < 16; ++k) {
        const int i4   = k * 256 + tid;      // float4 idx within batch
        const int eoff = i4 * 4;
        const float4 e4 = sp4[i4];
        const float4 a4 = lp4[i4];

        const int lidx = (eoff + N - 1) & (N - 1);
        const int ridx = (eoff + 4) & (N - 1);
        const float wl = fmaf(gS, sp[lidx], og * lp[lidx]);
        const float wr = fmaf(gS, sp[ridx], og * lp[ridx]);

        float4 w;
        w.x = fmaf(gS, e4.x, og * a4.x);
        w.y = fmaf(gS, e4.y, og * a4.y);
        w.z = fmaf(gS, e4.z, og * a4.z);
        w.w = fmaf(gS, e4.w, og * a4.w);

        float4 p;
        p.x = __powf(s0 * wl  + s1 * w.x + s2 * w.y, sh);
        p.y = __powf(s0 * w.x + s1 * w.y + s2 * w.z, sh);
        p.z = __powf(s0 * w.y + s1 * w.z + s2 * w.w, sh);
        p.w = __powf(s0 * w.z + s1 * w.w + s2 * wr,  sh);
        p4[k] = p;
        psum += p.x + p.y + p.z + p.w;
    }

    // deterministic block reduce of psum
#pragma unroll
    for (int o = 16; o > 0; o >>= 1)
        psum += __shfl_xor_sync(FULLM, psum, o);
    if (lane == 0) sred[tid >> 5] = psum;
    __syncthreads();
    if (tid == 0) {
        float x = 0.0f;
#pragma unroll
        for (int w = 0; w < 8; ++w) x += sred[w];
        sbc = x;
    }
    __syncthreads();
    const float invP = 1.0f / (sbc + 1e-16f);

    float4* op4 = reinterpret_cast<float4*>(out + (size_t)b * N);
#pragma unroll
    for (int k = 0; k < 16; ++k) {
        float4 p = p4[k];
        p.x *= invP; p.y *= invP; p.z *= invP; p.w *= invP;
        op4[k * 256 + tid] = p;
    }
}

extern "C" void kernel_launch(void* const* d_in, const int* in_sizes, int n_in,
                              void* d_out, int out_size) {
    const float* key     = (const float*)d_in[0];
    const float* beta    = (const float*)d_in[1];
    const float* gate    = (const float*)d_in[2];
    const float* shift   = (const float*)d_in[3];
    const float* sharpen = (const float*)d_in[4];
    const float* last    = (const float*)d_in[5];
    const float* mem     = (const float*)d_in[6];
    float* out = (float*)d_out;

    dim3 grid(N / 256, B);
    ntm_kernel<<<grid, 256>>>(key, beta, gate, shift, sharpen, last, mem, out);
}

// round 8
// speedup vs baseline: 1.2601x; 1.2204x over previous
#include <cuda_runtime.h>
#include <cooperative_groups.h>

namespace cg = cooperative_groups;

#define B 64
#define N 16384
#define M 64
#define FULLM 0xFFFFFFFFu

// scratch (device globals — no allocation allowed)
__device__ float g_s[B * N];       // exp(beta*cos) from k1
__device__ float g_part[B * 64];   // per-block partial sums of exp (k1 grid.x = 64)

// ---------------------------------------------------------------------------
// k1 (identical to R4 best): exp(beta*cos) per row + deterministic per-block
// partial sum. 4 lanes/row, lane loads 4x float4; 4 rows/thread -> 16
// LDG.128.CS in flight. Block = 256 thr -> 256 rows. Grid = (64, B).
// ---------------------------------------------------------------------------
__global__ __launch_bounds__(256) void k1_logits(
    const float* __restrict__ key,    // [B, M]
    const float* __restrict__ beta,   // [B, 1]
    const float* __restrict__ mem)    // [B, N, M]
{
    const int b    = blockIdx.y;
    const int tid  = threadIdx.x;
    const int l    = tid & 3;
    const int grp  = tid >> 2;
    const int row0 = blockIdx.x * 256;

    const float4* kp = reinterpret_cast<const float4*>(key + b * M);
    float4 k4[4];
#pragma unroll
    for (int j = 0; j < 4; ++j) k4[j] = kp[l + 4 * j];

    float ks = 0.0f;
#pragma unroll
    for (int j = 0; j < 4; ++j)
        ks += k4[j].x * k4[j].x + k4[j].y * k4[j].y
            + k4[j].z * k4[j].z + k4[j].w * k4[j].w;

    float4 m4[4][4];
#pragma unroll
    for (int u = 0; u < 4; ++u) {
        const int row = row0 + u * 64 + grp;
        const float4* mp = reinterpret_cast<const float4*>(
            mem + ((size_t)b * N + row) * M);
#pragma unroll
        for (int j = 0; j < 4; ++j) m4[u][j] = __ldcs(mp + l + 4 * j);
    }

    float dt[4] = {0.f, 0.f, 0.f, 0.f}, ms[4] = {0.f, 0.f, 0.f, 0.f};
#pragma unroll
    for (int u = 0; u < 4; ++u)
#pragma unroll
        for (int j = 0; j < 4; ++j) {
            dt[u] += k4[j].x * m4[u][j].x + k4[j].y * m4[u][j].y
                   + k4[j].z * m4[u][j].z + k4[j].w * m4[u][j].w;
            ms[u] += m4[u][j].x * m4[u][j].x + m4[u][j].y * m4[u][j].y
                   + m4[u][j].z * m4[u][j].z + m4[u][j].w * m4[u][j].w;
        }

#pragma unroll
    for (int off = 1; off <= 2; off <<= 1) {
        ks += __shfl_xor_sync(FULLM, ks, off);
#pragma unroll
        for (int u = 0; u < 4; ++u) {
            dt[u] += __shfl_xor_sync(FULLM, dt[u], off);
            ms[u] += __shfl_xor_sync(FULLM, ms[u], off);
        }
    }

    float esum = 0.0f;
    if (l == 0) {
        const float kn = sqrtf(ks);
        const float be = __ldg(beta + b);
#pragma unroll
        for (int u = 0; u < 4; ++u) {
            const int row = row0 + u * 64 + grp;
            const float denom = fmaxf(kn * sqrtf(ms[u]), 1e-8f);
            const float e = __expf(be * (dt[u] / denom));
            g_s[b * N + row] = e;
            esum += e;
        }
    }

    __shared__ float sred[8];
#pragma unroll
    for (int o = 16; o > 0; o >>= 1)
        esum += __shfl_xor_sync(FULLM, esum, o);
    if ((tid & 31) == 0) sred[tid >> 5] = esum;
    __syncthreads();
    if (tid == 0) {
        float s = 0.0f;
#pragma unroll
        for (int w = 0; w < 8; ++w) s += sred[w];
        g_part[b * 64 + blockIdx.x] = s;
    }
}

// ---------------------------------------------------------------------------
// k2: epilogue with 4-CTA clusters — one cluster per batch, each CTA handles
// 4096 elems (4 float4 per thread, 256 thr). Softmax denom from k1 partials;
// gate + circular 3-tap (elementwise recompute) + pow; renorm sum combined
// across the cluster via DSMEM in fixed rank order (deterministic).
// ---------------------------------------------------------------------------
__global__ __launch_bounds__(256) __cluster_dims__(4, 1, 1)
void k2_address(
    const float* __restrict__ gate,     // [B,1]
    const float* __restrict__ shift,    // [B,3]
    const float* __restrict__ sharpen,  // [B,1]
    const float* __restrict__ last,     // [B,N]
    float* __restrict__ out)            // [B,N]
{
    cg::cluster_group cluster = cg::this_cluster();

    const int cta = blockIdx.x;      // 0..255
    const int b   = cta >> 2;
    const int q   = cta & 3;         // quarter of the batch (== cluster rank)
    const int tid = threadIdx.x;
    const int lane = tid & 31;

    __shared__ float sred[8];
    __shared__ float sS;
    __shared__ float cpsum;          // this CTA's renorm partial (DSMEM target)

    // ---- softmax denominator from k1 partials (warp 0) ----
    if (tid < 32) {
        float S = g_part[b * 64 + tid] + g_part[b * 64 + 32 + tid];
#pragma unroll
        for (int o = 16; o > 0; o >>= 1)
            S += __shfl_xor_sync(FULLM, S, o);
        if (tid == 0) sS = S;
    }

    // ---- front-batched loads: 4 float4 of exp + 4 of last ----
    const int base4 = (b << 12) + (q << 10);   // float4 index of this CTA's span
    const float4* sp4 = reinterpret_cast<const float4*>(g_s);
    const float4* lp4 = reinterpret_cast<const float4*>(last);
    float4 e4[4], a4[4];
#pragma unroll
    for (int k = 0; k < 4; ++k) {
        e4[k] = sp4[base4 + k * 256 + tid];
        a4[k] = lp4[base4 + k * 256 + tid];
    }
    __syncthreads();

    const float g  = __ldg(gate + b);
    const float gS = g / sS;
    const float og = 1.0f - g;
    const float s0 = __ldg(shift + b * 3 + 0);
    const float s1 = __ldg(shift + b * 3 + 1);
    const float s2 = __ldg(shift + b * 3 + 2);
    const float sh = __ldg(sharpen + b);

    const float* sp = g_s  + b * N;
    const float* lp = last + (size_t)b * N;

    float4 p4[4];
    float psum = 0.0f;
#pragma unroll
    for (int k = 0; k < 4; ++k) {
        const int li4  = (q << 10) + k * 256 + tid;  // batch-local float4 idx
        const int eoff = li4 * 4;
        const int lidx = (eoff + N - 1) & (N - 1);
        const int ridx = (eoff + 4) & (N - 1);
        const float wl = fmaf(gS, sp[lidx], og * lp[lidx]);
        const float wr = fmaf(gS, sp[ridx], og * lp[ridx]);

        float4 w;
        w.x = fmaf(gS, e4[k].x, og * a4[k].x);
        w.y = fmaf(gS, e4[k].y, og * a4[k].y);
        w.z = fmaf(gS, e4[k].z, og * a4[k].z);
        w.w = fmaf(gS, e4[k].w, og * a4[k].w);

        float4 p;
        p.x = __powf(s0 * wl  + s1 * w.x + s2 * w.y, sh);
        p.y = __powf(s0 * w.x + s1 * w.y + s2 * w.z, sh);
        p.z = __powf(s0 * w.y + s1 * w.z + s2 * w.w, sh);
        p.w = __powf(s0 * w.z + s1 * w.w + s2 * wr,  sh);
        p4[k] = p;
        psum += p.x + p.y + p.z + p.w;
    }

    // ---- CTA-level psum reduce (deterministic) ----
#pragma unroll
    for (int o = 16; o > 0; o >>= 1)
        psum += __shfl_xor_sync(FULLM, psum, o);
    if (lane == 0) sred[tid >> 5] = psum;
    __syncthreads();
    if (tid == 0) {
        float x = 0.0f;
#pragma unroll
        for (int w = 0; w < 8; ++w) x += sred[w];
        cpsum = x;
    }

    // ---- cluster-level combine via DSMEM (fixed rank order) ----
    cluster.sync();
    float P = 0.0f;
#pragma unroll
    for (int r = 0; r < 4; ++r) {
        const float* peer = cluster.map_shared_rank(&cpsum, r);
        P += *peer;
    }
    cluster.sync();  // keep peers' smem alive until everyone has read

    const float invP = 1.0f / (P + 1e-16f);

    float4* op4 = reinterpret_cast<float4*>(out);
#pragma unroll
    for (int k = 0; k < 4; ++k) {
        float4 p = p4[k];
        p.x *= invP; p.y *= invP; p.z *= invP; p.w *= invP;
        op4[base4 + k * 256 + tid] = p;
    }
}

extern "C" void kernel_launch(void* const* d_in, const int* in_sizes, int n_in,
                              void* d_out, int out_size) {
    const float* key     = (const float*)d_in[0];
    const float* beta    = (const float*)d_in[1];
    const float* gate    = (const float*)d_in[2];
    const float* shift   = (const float*)d_in[3];
    const float* sharpen = (const float*)d_in[4];
    const float* last    = (const float*)d_in[5];
    const float* mem     = (const float*)d_in[6];
    float* out = (float*)d_out;

    dim3 g1(N / 256, B);
    k1_logits<<<g1, 256>>>(key, beta, mem);
    k2_address<<<B * 4, 256>>>(gate, shift, sharpen, last, out);
}